// round 1
// baseline (speedup 1.0000x reference)
#include <cuda_runtime.h>

// CLUBv2: mi = BETA * sum_d Var_d(y[:, d])
// y: [1024, 256] fp32 row-major. Output: 1 fp32 scalar.
//
// Algebraic reduction of the O(N^2 D) reference:
//   mean_i mean_j (y_jd - y_id)^2 = 2 * (E[y^2]_d - mu_d^2)
//   mi = 0.5 * sum_d of that = sum_d Var_d, then * BETA.

#define N_ROWS 1024
#define N_COLS 256
#define GRID   128
#define ROWS_PER_BLOCK (N_ROWS / GRID)   // 8
#define BETA_F 0.001f

__device__ float        g_ps[GRID * N_COLS];   // per-block per-column sum
__device__ float        g_pq[GRID * N_COLS];   // per-block per-column sumsq
__device__ unsigned int g_ticket = 0;

__global__ void __launch_bounds__(N_COLS, 1)
club_var_kernel(const float* __restrict__ y, float* __restrict__ out) {
    const int t = threadIdx.x;   // column index 0..255
    const int b = blockIdx.x;

    // Phase 1: each block accumulates 8 rows for its column set.
    // Loads are fully coalesced: consecutive t -> consecutive addresses.
    float s = 0.0f, q = 0.0f;
    const int row0 = b * ROWS_PER_BLOCK;
    #pragma unroll
    for (int r = 0; r < ROWS_PER_BLOCK; ++r) {
        float v = y[(row0 + r) * N_COLS + t];
        s += v;
        q = fmaf(v, v, q);
    }
    g_ps[b * N_COLS + t] = s;
    g_pq[b * N_COLS + t] = q;
    __threadfence();

    // Ticket: last block to arrive does the final reduction.
    __shared__ bool is_last;
    __shared__ float red[N_COLS];
    __syncthreads();
    if (t == 0) {
        unsigned int c = atomicAdd(&g_ticket, 1u);
        is_last = (c == (unsigned int)(GRID - 1));
    }
    __syncthreads();

    if (is_last) {
        // Phase 2: thread t sums column t's partials across all blocks.
        // g_ps[bb*256 + t]: fixed bb, consecutive t -> coalesced.
        float S = 0.0f, Q = 0.0f;
        #pragma unroll 8
        for (int bb = 0; bb < GRID; ++bb) {
            S += g_ps[bb * N_COLS + t];
            Q += g_pq[bb * N_COLS + t];
        }
        const float invN = 1.0f / (float)N_ROWS;
        const float mu = S * invN;
        float c = fmaf(-mu, mu, Q * invN);   // Var_d = E[y^2] - mu^2

        // Block-wide sum over d.
        red[t] = c;
        __syncthreads();
        #pragma unroll
        for (int off = N_COLS / 2; off >= 32; off >>= 1) {
            if (t < off) red[t] += red[t + off];
            __syncthreads();
        }
        if (t < 32) {
            float v = red[t];
            #pragma unroll
            for (int off = 16; off > 0; off >>= 1)
                v += __shfl_down_sync(0xFFFFFFFFu, v, off);
            if (t == 0) {
                out[0] = v * BETA_F;
                g_ticket = 0;   // reset for next graph replay (deterministic)
            }
        }
    }
}

extern "C" void kernel_launch(void* const* d_in, const int* in_sizes, int n_in,
                              void* d_out, int out_size) {
    (void)in_sizes; (void)n_in; (void)out_size;
    const float* y = (const float*)d_in[0];
    float* out = (float*)d_out;
    club_var_kernel<<<GRID, N_COLS>>>(y, out);
}

// round 2
// speedup vs baseline: 1.5018x; 1.5018x over previous
#include <cuda_runtime.h>

// CLUBv2: mi = BETA * sum_d Var_d(y[:, d])
// y: [1024, 256] fp32 row-major. Output: 1 fp32 scalar.
//
// Algebraic reduction of the O(N^2 D) reference:
//   mean_i mean_j (y_jd - y_id)^2 = 2 * (E[y^2]_d - mu_d^2)
//   mi = 0.5 * sum_d of that = sum_d Var_d, then * BETA.
//
// Cross-block combine uses 2^26 fixed-point int64 atomics: exactly
// associative -> deterministic across graph replays, and shrinks the
// final-block read from 256 KB (R1 design) to 4 KB.

#define N_ROWS 1024
#define N_COLS 256
#define GRID   128
#define ROWS_PER_BLOCK (N_ROWS / GRID)   // 8
#define BETA_F 0.001f
#define FIX_SCALE 67108864.0f            // 2^26
#define FIX_INV   (1.0f / 67108864.0f)

__device__ long long    g_S[N_COLS];     // fixed-point column sums
__device__ long long    g_Q[N_COLS];     // fixed-point column sum-of-squares
__device__ unsigned int g_ticket = 0;
// Note: g_S/g_Q start zeroed (static init); the finishing block re-zeros
// them after consuming, so every graph replay sees zeros. Deterministic.

__global__ void __launch_bounds__(N_COLS, 1)
club_var_kernel(const float* __restrict__ y, float* __restrict__ out) {
    const int t = threadIdx.x;   // column index 0..255
    const int b = blockIdx.x;

    // Phase 1: each block accumulates 8 rows of its column. Coalesced.
    float s = 0.0f, q = 0.0f;
    const int row0 = b * ROWS_PER_BLOCK;
    #pragma unroll
    for (int r = 0; r < ROWS_PER_BLOCK; ++r) {
        float v = y[(row0 + r) * N_COLS + t];
        s += v;
        q = fmaf(v, v, q);
    }

    // Deterministic cross-block combine: integer REDs, 256 distinct addrs.
    atomicAdd((unsigned long long*)&g_S[t],
              (unsigned long long)(long long)llrintf(s * FIX_SCALE));
    atomicAdd((unsigned long long*)&g_Q[t],
              (unsigned long long)(long long)llrintf(q * FIX_SCALE));

    __threadfence();   // order our REDs before the ticket arrival
    __shared__ bool is_last;
    __syncthreads();
    if (t == 0) {
        unsigned int c = atomicAdd(&g_ticket, 1u);
        is_last = (c == (unsigned int)(GRID - 1));
    }
    __syncthreads();

    if (is_last) {
        // Phase 2: only 4 KB to read. Thread t owns column t.
        long long Sf = g_S[t];
        long long Qf = g_Q[t];
        g_S[t] = 0;            // reset for next graph replay
        g_Q[t] = 0;

        const float S = (float)Sf * FIX_INV;
        const float Q = (float)Qf * FIX_INV;
        const float invN = 1.0f / (float)N_ROWS;
        const float mu = S * invN;
        float c = fmaf(-mu, mu, Q * invN);   // Var_d

        __shared__ float red[N_COLS];
        red[t] = c;
        __syncthreads();
        #pragma unroll
        for (int off = N_COLS / 2; off >= 32; off >>= 1) {
            if (t < off) red[t] += red[t + off];
            __syncthreads();
        }
        if (t < 32) {
            float v = red[t];
            #pragma unroll
            for (int off = 16; off > 0; off >>= 1)
                v += __shfl_down_sync(0xFFFFFFFFu, v, off);
            if (t == 0) {
                out[0] = v * BETA_F;
                g_ticket = 0;   // reset for next graph replay
            }
        }
    }
}

extern "C" void kernel_launch(void* const* d_in, const int* in_sizes, int n_in,
                              void* d_out, int out_size) {
    (void)in_sizes; (void)n_in; (void)out_size;
    const float* y = (const float*)d_in[0];
    float* out = (float*)d_out;
    club_var_kernel<<<GRID, N_COLS>>>(y, out);
}

// round 3
// speedup vs baseline: 1.9567x; 1.3029x over previous
#include <cuda_runtime.h>

// CLUBv2: mi = BETA * sum_d Var_d(y[:, d])
// y: [1024, 256] fp32 row-major. Output: 1 fp32 scalar.
//
//   mean_i mean_j (y_jd - y_id)^2 = 2 * (E[y^2]_d - mu_d^2)
//   mi = sum_d Var_d * BETA
//
// Cross-block combine: 2^26 fixed-point int64 relaxed REDs (exactly
// associative -> deterministic). Visibility via ONE acq_rel ticket atomic
// per block (no MEMBAR.GPU drain). Grid=32 minimizes arrivals/skew.

#define N_ROWS 1024
#define N_COLS 256
#define GRID   32
#define ROWS_PER_BLOCK (N_ROWS / GRID)   // 32
#define BETA_F 0.001f
#define FIX_SCALE 67108864.0f            // 2^26
#define FIX_INV   (1.0f / 67108864.0f)

__device__ long long    g_S[N_COLS];     // fixed-point column sums
__device__ long long    g_Q[N_COLS];     // fixed-point column sum-of-squares
__device__ unsigned int g_ticket = 0;
// g_S/g_Q start zeroed; the finishing block re-zeros them after consuming,
// so every graph replay sees zeros. Deterministic.

__device__ __forceinline__ unsigned int atom_add_acq_rel(unsigned int* addr,
                                                         unsigned int v) {
    unsigned int old;
    asm volatile("atom.acq_rel.gpu.global.add.u32 %0, [%1], %2;"
                 : "=r"(old) : "l"(addr), "r"(v) : "memory");
    return old;
}

__global__ void __launch_bounds__(N_COLS, 1)
club_var_kernel(const float* __restrict__ y, float* __restrict__ out) {
    const int t = threadIdx.x;   // column index 0..255
    const int b = blockIdx.x;

    // Phase 1: 32 rows per block, coalesced scalar loads, high MLP.
    float s = 0.0f, q = 0.0f;
    const float* p = y + (size_t)b * ROWS_PER_BLOCK * N_COLS + t;
    #pragma unroll
    for (int r = 0; r < ROWS_PER_BLOCK; ++r) {
        float v = p[r * N_COLS];
        s += v;
        q = fmaf(v, v, q);
    }

    // Relaxed fire-and-forget REDs: deterministic (integer, associative).
    atomicAdd((unsigned long long*)&g_S[t],
              (unsigned long long)(long long)llrintf(s * FIX_SCALE));
    atomicAdd((unsigned long long*)&g_Q[t],
              (unsigned long long)(long long)llrintf(q * FIX_SCALE));

    // One acq_rel ticket per block: releases our REDs, acquires others'.
    __shared__ bool is_last;
    __syncthreads();                 // all REDs of this block issued
    if (t == 0)
        is_last = (atom_add_acq_rel(&g_ticket, 1u) == (unsigned)(GRID - 1));
    __syncthreads();

    if (is_last) {
        // Phase 2: 4 KB from L2 (bypass L1 to be safe vs stale lines).
        long long Sf = __ldcg(&g_S[t]);
        long long Qf = __ldcg(&g_Q[t]);
        g_S[t] = 0;                  // reset for next graph replay
        g_Q[t] = 0;

        const float S = (float)Sf * FIX_INV;
        const float Q = (float)Qf * FIX_INV;
        const float invN = 1.0f / (float)N_ROWS;
        const float mu = S * invN;
        float c = fmaf(-mu, mu, Q * invN);   // Var_d

        // Warp-shuffle reduce, then 8 partials through smem, warp 0 finishes.
        #pragma unroll
        for (int off = 16; off > 0; off >>= 1)
            c += __shfl_down_sync(0xFFFFFFFFu, c, off);

        __shared__ float wsum[8];
        const int warp = t >> 5, lane = t & 31;
        if (lane == 0) wsum[warp] = c;
        __syncthreads();
        if (warp == 0) {
            float v = (lane < 8) ? wsum[lane] : 0.0f;
            #pragma unroll
            for (int off = 4; off > 0; off >>= 1)
                v += __shfl_down_sync(0xFFFFFFFFu, v, off);
            if (lane == 0) {
                out[0] = v * BETA_F;
                g_ticket = 0;        // reset for next graph replay
            }
        }
    }
}

extern "C" void kernel_launch(void* const* d_in, const int* in_sizes, int n_in,
                              void* d_out, int out_size) {
    (void)in_sizes; (void)n_in; (void)out_size;
    const float* y = (const float*)d_in[0];
    float* out = (float*)d_out;
    club_var_kernel<<<GRID, N_COLS>>>(y, out);
}